// round 3
// baseline (speedup 1.0000x reference)
#include <cuda_runtime.h>

#define N0 16
#define N1 200
#define N2 200
#define NPIX (N1*N2)          // 40000
#define NVOX (N0*NPIX)        // 640000
#define NPHI 190
#define NRAD 223
#define NT 351
#define GR 4                  // gaussian radius
#define NSLOT (NPHI*NRAD)     // 42370
#define NCH 8                 // phi chunks for backprojection
#define CHW 24                // ceil(190/8)

// ---------------- scratch (device globals; no allocation allowed) ----------
__device__ __align__(16) float d_GW[2*GR+1];
__device__ float d_COS[NPHI];
__device__ float d_SIN[NPHI];
__device__ float d_RV[NRAD];
__device__ __align__(16) float d_buf0[NVOX];
__device__ __align__(16) float d_buf1[NVOX];
__device__ __align__(16) float d_st2[2*NVOX];         // paired smoothed img: [(i,j)][{j,j+1}][z]
__device__ __align__(16) float d_pp[2*N0*NSLOT];      // partial projections [half][z][sidx]
__device__ __align__(16) float d_zr[NSLOT*N0];        // mult*data/exp, [phi][rad][z]
__device__ __align__(16) float d_bp[NCH*NVOX];        // backprojection partials

// ---------------- constant tables (match numpy float64 -> float32) ---------
__global__ void k_init()
{
    int t = blockIdx.x * blockDim.x + threadIdx.x;
    if (t == 0) {
        const double sigma = 4.5 / (2.35 * 2.0);
        double g[2*GR+1];
        double sum = 0.0;
        for (int k = 0; k <= 2*GR; k++) {
            double d = (double)(k - GR) / sigma;
            g[k] = exp(-0.5 * d * d);
            sum += g[k];
        }
        for (int k = 0; k <= 2*GR; k++) d_GW[k] = (float)(g[k] / sum);
    }
    const double PI = 3.14159265358979323846;
    for (int i = t; i < NPHI; i += blockDim.x * gridDim.x) {
        float phi = (float)((double)i * (PI / 190.0));   // linspace f64 -> f32
        d_COS[i] = (float)cos((double)phi);
        d_SIN[i] = (float)sin((double)phi);
    }
    for (int i = t; i < NRAD; i += blockDim.x * gridDim.x) {
        d_RV[i] = (float)(-200.0 + (double)i * (400.0 / 222.0));
    }
}

// ---------------- gaussian smoothing (self-adjoint, symmetric padding) -----
__device__ __forceinline__ int refl(int m, int n)
{
    if (m < 0)  m = -1 - m;
    if (m >= n) m = 2*n - 1 - m;
    return m;
}

// smooth along z (axis0). one thread per pixel; all 16 z in registers.
__global__ void k_smooth_z(const float* __restrict__ in, float* __restrict__ out)
{
    int pix = blockIdx.x * blockDim.x + threadIdx.x;
    if (pix >= NPIX) return;
    float v[N0];
    #pragma unroll
    for (int z = 0; z < N0; z++) v[z] = in[z*NPIX + pix];
    #pragma unroll
    for (int z = 0; z < N0; z++) {
        float s = 0.f;
        #pragma unroll
        for (int d = -GR; d <= GR; d++) {
            int m = z + d;
            if (m < 0)  m = -1 - m;
            if (m >= N0) m = 2*N0 - 1 - m;
            s += d_GW[d+GR] * v[m];
        }
        out[z*NPIX + pix] = s;
    }
}

// smooth along i (axis1), layout [z][i][j]
__global__ void k_smooth_i(const float* __restrict__ in, float* __restrict__ out)
{
    int t = blockIdx.x * blockDim.x + threadIdx.x;
    if (t >= NVOX) return;
    int j = t % N2;
    int i = (t / N2) % N1;
    int z = t / NPIX;
    const float* base = in + z*NPIX + j;
    float s = 0.f;
    if (i >= GR && i < N1-GR) {
        #pragma unroll
        for (int d = -GR; d <= GR; d++)
            s += d_GW[d+GR] * base[(i+d) * N2];
    } else {
        #pragma unroll
        for (int d = -GR; d <= GR; d++)
            s += d_GW[d+GR] * base[refl(i+d, N1) * N2];
    }
    out[t] = s;
}

// smooth along j (axis2), layout [z][i][j] -> same layout
__global__ void k_smooth_j(const float* __restrict__ in, float* __restrict__ out)
{
    int t = blockIdx.x * blockDim.x + threadIdx.x;
    if (t >= NVOX) return;
    int j = t % N2;
    int i = (t / N2) % N1;
    int z = t / NPIX;
    const float* base = in + z*NPIX + i*N2;
    float s = 0.f;
    if (j >= GR && j < N2-GR) {
        #pragma unroll
        for (int d = -GR; d <= GR; d++)
            s += d_GW[d+GR] * base[j+d];
    } else {
        #pragma unroll
        for (int d = -GR; d <= GR; d++)
            s += d_GW[d+GR] * base[refl(j+d, N2)];
    }
    out[t] = s;
}

// smooth along j, writing PAIRED z-innermost transposed output:
// out2[((i*N2+j)*2 + 0)*N0 + z] = v(i, j,   z)
// out2[((i*N2+j)*2 + 1)*N0 + z] = v(i, j+1, z)   (j+1 clamped at N2-1)
__global__ void k_smooth_j_t2(const float* __restrict__ in, float* __restrict__ out2)
{
    int t = blockIdx.x * blockDim.x + threadIdx.x;
    if (t >= NVOX) return;
    int j = t % N2;
    int i = (t / N2) % N1;
    int z = t / NPIX;
    const float* base = in + z*NPIX + i*N2;
    float s = 0.f;
    if (j >= GR && j < N2-GR) {
        #pragma unroll
        for (int d = -GR; d <= GR; d++)
            s += d_GW[d+GR] * base[j+d];
    } else {
        #pragma unroll
        for (int d = -GR; d <= GR; d++)
            s += d_GW[d+GR] * base[refl(j+d, N2)];
    }
    int pj = (i*N2 + j) << 1;
    out2[pj*N0 + z] = s;                                   // part0 of j
    if (j > 0)      out2[(pj - 1)*N0 + z] = s;             // part1 of j-1 ( (i,j-1)*2+1 )
    if (j == N2-1)  out2[(pj + 1)*N0 + z] = s;             // clamp dup: part1 of j
}

// ---------------- forward projection (partial halves) -----------------------
// one thread = (phi, rad, z-quad, t-half). st2 layout gives both j-corners of a
// row in one 128B-aligned block -> 2 L1 lines per sample instead of 4.
__global__ void k_project(const float* __restrict__ st2, float* __restrict__ pp)
{
    int t = blockIdx.x * blockDim.x + threadIdx.x;
    if (t >= NSLOT * 8) return;
    int zq   = t & 3;
    int half = (t >> 2) & 1;
    int ray  = t >> 3;
    int phi = ray / NRAD;
    int rad = ray - phi * NRAD;

    float c = d_COS[phi], s = d_SIN[phi];
    float r = d_RV[rad];
    float rns = r * (-s);
    float rc  = r * c;

    // ix(n) = A + n*c, iy(n) = B + n*s  (voxel units, n = t sample index)
    float A = 0.5f * (rns + 199.f) - 175.f * c;
    float B = 0.5f * (rc  + 199.f) - 175.f * s;

    const float EPS = 1e-6f;
    float lo = 0.f, hi = 350.f;
    bool empty = false;
    if (fabsf(c) > EPS) {
        float n0 = (0.f   - A) / c;
        float n1 = (199.f - A) / c;
        float l = fminf(n0, n1), h = fmaxf(n0, n1);
        lo = fmaxf(lo, l); hi = fminf(hi, h);
    } else if (A < 0.f || A > 199.f) empty = true;
    if (fabsf(s) > EPS) {
        float n0 = (0.f   - B) / s;
        float n1 = (199.f - B) / s;
        float l = fminf(n0, n1), h = fmaxf(n0, n1);
        lo = fmaxf(lo, l); hi = fminf(hi, h);
    } else if (B < 0.f || B > 199.f) empty = true;

    float a0 = 0.f, a1 = 0.f, a2 = 0.f, a3 = 0.f;
    if (!empty && hi >= lo) {
        int nlo = max(0,    (int)floorf(lo) - 1);
        int nhi = min(NT-1, (int)ceilf (hi) + 1);
        int mid = (nlo + nhi + 1) >> 1;
        int nb  = half ? mid : nlo;
        int ne  = half ? nhi : mid - 1;
        for (int n = nb; n <= ne; n++) {
            float tn = -350.f + 2.f * (float)n;
            float ix = (__fmaf_rn(tn, c, rns) + 199.f) * 0.5f;
            float iy = (__fmaf_rn(tn, s, rc ) + 199.f) * 0.5f;
            if (ix < 0.f || ix > 199.f || iy < 0.f || iy > 199.f) continue;
            int i0 = (int)ix;           // floor, ix >= 0
            int j0 = (int)iy;
            float fi = ix - (float)i0;
            float fj = iy - (float)j0;
            int i1 = min(i0 + 1, N1 - 1);
            const float4* p0 = (const float4*)(st2 + ((unsigned)(i0*N2 + j0) << 5));
            const float4* p1 = (const float4*)(st2 + ((unsigned)(i1*N2 + j0) << 5));
            float4 c00 = p0[zq];
            float4 c01 = p0[4 + zq];
            float4 c10 = p1[zq];
            float4 c11 = p1[4 + zq];
            float w00 = (1.f-fi)*(1.f-fj);
            float w10 = fi*(1.f-fj);
            float w01 = (1.f-fi)*fj;
            float w11 = fi*fj;
            a0 += w00*c00.x + w10*c10.x + w01*c01.x + w11*c11.x;
            a1 += w00*c00.y + w10*c10.y + w01*c01.y + w11*c11.y;
            a2 += w00*c00.z + w10*c10.z + w01*c01.z + w11*c11.z;
            a3 += w00*c00.w + w10*c10.w + w01*c01.w + w11*c11.w;
        }
    }

    int sidx = phi * NRAD + rad;
    float* dst = pp + (half*N0 + zq*4)*NSLOT + sidx;
    dst[0*NSLOT] = a0;
    dst[1*NSLOT] = a1;
    dst[2*NSLOT] = a2;
    dst[3*NSLOT] = a3;
}

// ---------------- combine halves + exp + ratio -------------------------------
__global__ void k_ratio(const float* __restrict__ pp,
                        const float* __restrict__ data,
                        const float* __restrict__ contam,
                        const float* __restrict__ mult,
                        float* __restrict__ zr)
{
    int sidx = blockIdx.x * blockDim.x + threadIdx.x;
    if (sidx >= NSLOT) return;
    #pragma unroll
    for (int z = 0; z < N0; z++) {
        float proj = (pp[z*NSLOT + sidx] + pp[(N0+z)*NSLOT + sidx]) * 2.f;
        int gi = z*NSLOT + sidx;
        float mm = mult[gi];
        float e  = __fmaf_rn(mm, proj, contam[gi]);   // exp = mult*fwd + contam
        zr[sidx*N0 + z] = mm * data[gi] / e;          // mult * (data/exp)
    }
}

// ---------------- backprojection (exact adjoint, gather form) ---------------
// one thread = (pixel, phi-chunk). All 16 z accumulated; W computed once.
__global__ void k_backproject(const float* __restrict__ zr, float* __restrict__ bp)
{
    int tid = blockIdx.x * blockDim.x + threadIdx.x;
    if (tid >= NCH * NPIX) return;
    int pix = tid % NPIX;
    int ch  = tid / NPIX;
    int i = pix / N2, j = pix % N2;
    float X = -199.f + 2.f * (float)i;
    float Y = -199.f + 2.f * (float)j;

    float acc[N0];
    #pragma unroll
    for (int k = 0; k < N0; k++) acc[k] = 0.f;

    const float inv_dr = (float)(222.0 / 400.0);
    float fi_f = (float)i, fj_f = (float)j;

    int plo = ch * CHW;
    int phi_end = min(NPHI, plo + CHW);

    for (int phi = plo; phi < phi_end; phi++) {
        float c = d_COS[phi], s = d_SIN[phi];
        float lim = 2.f * (fabsf(c) + fabsf(s)) + 1e-2f;   // tight tent support
        float r0 = -X*s + Y*c;   // projection of voxel onto perp(phi)
        float t0 =  X*c + Y*s;   // projection onto dir(phi)
        int mlo = max(0,      (int)ceilf ((r0 + 200.f - lim) * inv_dr));
        int mhi = min(NRAD-1, (int)floorf((r0 + 200.f + lim) * inv_dr));
        int nlo = max(0,      (int)ceilf ((t0 + 350.f - lim) * 0.5f));
        int nhi = min(NT-1,   (int)floorf((t0 + 350.f + lim) * 0.5f));
        for (int m = mlo; m <= mhi; m++) {
            float rm  = d_RV[m];
            float rns = rm * (-s);
            float rc  = rm * c;
            float W = 0.f;
            for (int n = nlo; n <= nhi; n++) {
                float tn = -350.f + 2.f * (float)n;
                float ix = (__fmaf_rn(tn, c, rns) + 199.f) * 0.5f; // same formula as fwd
                float iy = (__fmaf_rn(tn, s, rc ) + 199.f) * 0.5f;
                if (ix < 0.f || ix > 199.f || iy < 0.f || iy > 199.f) continue;
                float wx = 1.f - fabsf(ix - fi_f);
                float wy = 1.f - fabsf(iy - fj_f);
                if (wx > 0.f && wy > 0.f) W = __fmaf_rn(wx, wy, W);
            }
            if (W != 0.f) {
                const float4* zp = (const float4*)(zr + (phi*NRAD + m)*N0);
                float4 a = zp[0], b = zp[1], cc = zp[2], dd = zp[3];
                acc[0]  += W*a.x;  acc[1]  += W*a.y;  acc[2]  += W*a.z;  acc[3]  += W*a.w;
                acc[4]  += W*b.x;  acc[5]  += W*b.y;  acc[6]  += W*b.z;  acc[7]  += W*b.w;
                acc[8]  += W*cc.x; acc[9]  += W*cc.y; acc[10] += W*cc.z; acc[11] += W*cc.w;
                acc[12] += W*dd.x; acc[13] += W*dd.y; acc[14] += W*dd.z; acc[15] += W*dd.w;
            }
        }
    }
    float* dst = bp + ch * NVOX;
    #pragma unroll
    for (int k = 0; k < N0; k++)
        dst[k*NPIX + pix] = acc[k] * 2.f;   // * STEP
}

// ---------------- combine partial backprojections ---------------------------
__global__ void k_combine(const float* __restrict__ bp, float* __restrict__ g)
{
    int t = blockIdx.x * blockDim.x + threadIdx.x;
    if (t >= NVOX) return;
    float s = 0.f;
    #pragma unroll
    for (int c = 0; c < NCH; c++) s += bp[c*NVOX + t];
    g[t] = s;
}

// ---------------- final z-smoothing + MLEM update ---------------------------
__global__ void k_smooth_z_final(const float* __restrict__ gin,
                                 const float* __restrict__ x,
                                 const float* __restrict__ sens,
                                 float* __restrict__ out)
{
    int pix = blockIdx.x * blockDim.x + threadIdx.x;
    if (pix >= NPIX) return;
    float v[N0];
    #pragma unroll
    for (int z = 0; z < N0; z++) v[z] = gin[z*NPIX + pix];
    #pragma unroll
    for (int z = 0; z < N0; z++) {
        float s = 0.f;
        #pragma unroll
        for (int d = -GR; d <= GR; d++) {
            int m = z + d;
            if (m < 0)  m = -1 - m;
            if (m >= N0) m = 2*N0 - 1 - m;
            s += d_GW[d+GR] * v[m];
        }
        int gi = z*NPIX + pix;
        out[gi] = x[gi] * s / sens[gi];
    }
}

// ---------------- launch ----------------------------------------------------
extern "C" void kernel_launch(void* const* d_in, const int* in_sizes, int n_in,
                              void* d_out, int out_size)
{
    const float* x      = (const float*)d_in[0];
    const float* data   = (const float*)d_in[1];
    const float* contam = (const float*)d_in[2];
    const float* mult   = (const float*)d_in[3];
    const float* sens   = (const float*)d_in[4];
    float* out = (float*)d_out;

    float *buf0, *buf1, *st2, *pp, *zr, *bp;
    cudaGetSymbolAddress((void**)&buf0, d_buf0);
    cudaGetSymbolAddress((void**)&buf1, d_buf1);
    cudaGetSymbolAddress((void**)&st2,  d_st2);
    cudaGetSymbolAddress((void**)&pp,   d_pp);
    cudaGetSymbolAddress((void**)&zr,   d_zr);
    cudaGetSymbolAddress((void**)&bp,   d_bp);

    k_init<<<1, 256>>>();

    // forward: gauss3(x) -> paired transposed smoothed image
    k_smooth_z   <<<(NPIX + 255)/256, 256>>>(x, buf0);
    k_smooth_i   <<<(NVOX + 255)/256, 256>>>(buf0, buf1);
    k_smooth_j_t2<<<(NVOX + 255)/256, 256>>>(buf1, st2);

    // project (split t-halves) -> combine + exp + ratio
    k_project<<<(NSLOT*8 + 127)/128, 128>>>(st2, pp);
    k_ratio  <<<(NSLOT + 127)/128, 128>>>(pp, data, contam, mult, zr);

    // adjoint: backproject (phi-chunked), combine, then gauss3 reversed
    k_backproject<<<(NCH*NPIX + 255)/256, 256>>>(zr, bp);
    k_combine<<<(NVOX + 255)/256, 256>>>(bp, buf0);
    k_smooth_j<<<(NVOX + 255)/256, 256>>>(buf0, buf1);
    k_smooth_i<<<(NVOX + 255)/256, 256>>>(buf1, buf0);
    k_smooth_z_final<<<(NPIX + 255)/256, 256>>>(buf0, x, sens, out);
}

// round 4
// speedup vs baseline: 1.0332x; 1.0332x over previous
#include <cuda_runtime.h>

#define N0 16
#define N1 200
#define N2 200
#define NPIX (N1*N2)          // 40000
#define NVOX (N0*NPIX)        // 640000
#define NPHI 190
#define NRAD 223
#define NT 351
#define GR 4                  // gaussian radius
#define NSLOT (NPHI*NRAD)     // 42370
#define NCH 8                 // phi chunks for backprojection
#define CHW 24                // ceil(190/8)

// ---------------- scratch (device globals; no allocation allowed) ----------
__device__ __align__(16) float d_GW[2*GR+1];
__device__ float d_COS[NPHI];
__device__ float d_SIN[NPHI];
__device__ float d_RV[NRAD];
__device__ __align__(16) float d_buf0[NVOX];
__device__ __align__(16) float d_buf1[NVOX];
__device__ __align__(16) float d_st2[2*NVOX];         // paired smoothed img: [(i,j)][{j,j+1}][z]
__device__ __align__(16) float d_zr[NSLOT*N0];        // mult*data/exp, [sidx][z]
__device__ __align__(16) float d_bp[NCH*NVOX];        // backprojection partials

// ---------------- constant tables (match numpy float64 -> float32) ---------
__global__ void k_init()
{
    int t = blockIdx.x * blockDim.x + threadIdx.x;
    if (t == 0) {
        const double sigma = 4.5 / (2.35 * 2.0);
        double g[2*GR+1];
        double sum = 0.0;
        for (int k = 0; k <= 2*GR; k++) {
            double d = (double)(k - GR) / sigma;
            g[k] = exp(-0.5 * d * d);
            sum += g[k];
        }
        for (int k = 0; k <= 2*GR; k++) d_GW[k] = (float)(g[k] / sum);
    }
    const double PI = 3.14159265358979323846;
    for (int i = t; i < NPHI; i += blockDim.x * gridDim.x) {
        float phi = (float)((double)i * (PI / 190.0));   // linspace f64 -> f32
        d_COS[i] = (float)cos((double)phi);
        d_SIN[i] = (float)sin((double)phi);
    }
    for (int i = t; i < NRAD; i += blockDim.x * gridDim.x) {
        d_RV[i] = (float)(-200.0 + (double)i * (400.0 / 222.0));
    }
}

// ---------------- gaussian smoothing (self-adjoint, symmetric padding) -----
__device__ __forceinline__ int refl(int m, int n)
{
    if (m < 0)  m = -1 - m;
    if (m >= n) m = 2*n - 1 - m;
    return m;
}

// smooth along z (axis0). one thread per pixel; all 16 z in registers.
__global__ void k_smooth_z(const float* __restrict__ in, float* __restrict__ out)
{
    int pix = blockIdx.x * blockDim.x + threadIdx.x;
    if (pix >= NPIX) return;
    float v[N0];
    #pragma unroll
    for (int z = 0; z < N0; z++) v[z] = in[z*NPIX + pix];
    #pragma unroll
    for (int z = 0; z < N0; z++) {
        float s = 0.f;
        #pragma unroll
        for (int d = -GR; d <= GR; d++) {
            int m = z + d;
            if (m < 0)  m = -1 - m;
            if (m >= N0) m = 2*N0 - 1 - m;
            s += d_GW[d+GR] * v[m];
        }
        out[z*NPIX + pix] = s;
    }
}

// smooth along i (axis1), layout [z][i][j]
__global__ void k_smooth_i(const float* __restrict__ in, float* __restrict__ out)
{
    int t = blockIdx.x * blockDim.x + threadIdx.x;
    if (t >= NVOX) return;
    int j = t % N2;
    int i = (t / N2) % N1;
    int z = t / NPIX;
    const float* base = in + z*NPIX + j;
    float s = 0.f;
    if (i >= GR && i < N1-GR) {
        #pragma unroll
        for (int d = -GR; d <= GR; d++)
            s += d_GW[d+GR] * base[(i+d) * N2];
    } else {
        #pragma unroll
        for (int d = -GR; d <= GR; d++)
            s += d_GW[d+GR] * base[refl(i+d, N1) * N2];
    }
    out[t] = s;
}

// smooth along j (axis2), layout [z][i][j] -> same layout
__global__ void k_smooth_j(const float* __restrict__ in, float* __restrict__ out)
{
    int t = blockIdx.x * blockDim.x + threadIdx.x;
    if (t >= NVOX) return;
    int j = t % N2;
    int i = (t / N2) % N1;
    int z = t / NPIX;
    const float* base = in + z*NPIX + i*N2;
    float s = 0.f;
    if (j >= GR && j < N2-GR) {
        #pragma unroll
        for (int d = -GR; d <= GR; d++)
            s += d_GW[d+GR] * base[j+d];
    } else {
        #pragma unroll
        for (int d = -GR; d <= GR; d++)
            s += d_GW[d+GR] * base[refl(j+d, N2)];
    }
    out[t] = s;
}

// smooth along j, writing PAIRED z-innermost transposed output:
// out2[((i*N2+j)*2 + 0)*N0 + z] = v(i, j,   z)
// out2[((i*N2+j)*2 + 1)*N0 + z] = v(i, j+1, z)   (j+1 clamped at N2-1)
__global__ void k_smooth_j_t2(const float* __restrict__ in, float* __restrict__ out2)
{
    int t = blockIdx.x * blockDim.x + threadIdx.x;
    if (t >= NVOX) return;
    int j = t % N2;
    int i = (t / N2) % N1;
    int z = t / NPIX;
    const float* base = in + z*NPIX + i*N2;
    float s = 0.f;
    if (j >= GR && j < N2-GR) {
        #pragma unroll
        for (int d = -GR; d <= GR; d++)
            s += d_GW[d+GR] * base[j+d];
    } else {
        #pragma unroll
        for (int d = -GR; d <= GR; d++)
            s += d_GW[d+GR] * base[refl(j+d, N2)];
    }
    int pj = (i*N2 + j) << 1;
    out2[pj*N0 + z] = s;                                   // part0 of j
    if (j > 0)      out2[(pj - 1)*N0 + z] = s;             // part1 of j-1 ( (i,j-1)*2+1 )
    if (j == N2-1)  out2[(pj + 1)*N0 + z] = s;             // clamp dup: part1 of j
}

// ---------------- forward projection + ratio (fused) ------------------------
// 8 lanes per ray, all at the SAME sample n. The 8 lanes load the 8 float4s of
// one 128B pair-block in a single warp-LDG -> 1 wavefront per line, full 128B
// used. Lanes 0-3 accumulate the j0-weighted part (z-quads 0-3), lanes 4-7 the
// j1-weighted part; shfl-reduce at the end. Ratio computed in the epilogue.
__global__ void k_project(const float* __restrict__ st2,
                          const float* __restrict__ data,
                          const float* __restrict__ contam,
                          const float* __restrict__ mult,
                          float* __restrict__ zr)
{
    int t = blockIdx.x * blockDim.x + threadIdx.x;
    int lane8 = t & 7;
    int ray   = t >> 3;
    bool live = (ray < NSLOT);
    if (!live) ray = NSLOT - 1;           // clamp: keep all 32 lanes for shfl
    int phi = ray / NRAD;
    int rad = ray - phi * NRAD;
    int zq  = lane8 & 3;
    bool isj1 = lane8 >= 4;

    float c = d_COS[phi], s = d_SIN[phi];
    float r = d_RV[rad];
    float rns = r * (-s);
    float rc  = r * c;

    // ix(n) = A + n*c, iy(n) = B + n*s  (voxel units, n = t sample index)
    float A = 0.5f * (rns + 199.f) - 175.f * c;
    float B = 0.5f * (rc  + 199.f) - 175.f * s;

    const float EPS = 1e-6f;
    float lo = 0.f, hi = 350.f;
    bool empty = false;
    if (fabsf(c) > EPS) {
        float n0 = (0.f   - A) / c;
        float n1 = (199.f - A) / c;
        lo = fmaxf(lo, fminf(n0, n1)); hi = fminf(hi, fmaxf(n0, n1));
    } else if (A < 0.f || A > 199.f) empty = true;
    if (fabsf(s) > EPS) {
        float n0 = (0.f   - B) / s;
        float n1 = (199.f - B) / s;
        lo = fmaxf(lo, fminf(n0, n1)); hi = fminf(hi, fmaxf(n0, n1));
    } else if (B < 0.f || B > 199.f) empty = true;

    float4 acc = make_float4(0.f, 0.f, 0.f, 0.f);
    if (!empty && hi >= lo) {
        int nlo = max(0,    (int)floorf(lo) - 1);
        int nhi = min(NT-1, (int)ceilf (hi) + 1);
        for (int n = nlo; n <= nhi; n++) {
            float tn = -350.f + 2.f * (float)n;
            float ix = (__fmaf_rn(tn, c, rns) + 199.f) * 0.5f;
            float iy = (__fmaf_rn(tn, s, rc ) + 199.f) * 0.5f;
            if (ix < 0.f || ix > 199.f || iy < 0.f || iy > 199.f) continue;
            int i0 = (int)ix;           // floor, ix >= 0
            int j0 = (int)iy;
            float fi = ix - (float)i0;
            float fj = iy - (float)j0;
            float wj = isj1 ? fj : (1.f - fj);
            unsigned base = ((unsigned)(i0*N2 + j0)) << 5;        // floats
            unsigned iofs = (i0 < N1-1) ? (unsigned)(N2*2*N0) : 0u;
            const float4* p0 = (const float4*)(st2 + base) + lane8;
            const float4* p1 = (const float4*)(st2 + base + iofs) + lane8;
            float4 b0 = *p0;
            float4 b1 = *p1;
            float w0 = wj * (1.f - fi);
            float w1 = wj * fi;
            acc.x = __fmaf_rn(w0, b0.x, __fmaf_rn(w1, b1.x, acc.x));
            acc.y = __fmaf_rn(w0, b0.y, __fmaf_rn(w1, b1.y, acc.y));
            acc.z = __fmaf_rn(w0, b0.z, __fmaf_rn(w1, b1.z, acc.z));
            acc.w = __fmaf_rn(w0, b0.w, __fmaf_rn(w1, b1.w, acc.w));
        }
    }

    // combine j0 (lanes 0-3) with j1 (lanes 4-7)
    acc.x += __shfl_down_sync(0xffffffffu, acc.x, 4);
    acc.y += __shfl_down_sync(0xffffffffu, acc.y, 4);
    acc.z += __shfl_down_sync(0xffffffffu, acc.z, 4);
    acc.w += __shfl_down_sync(0xffffffffu, acc.w, 4);

    if (live && !isj1) {
        int sidx = ray;
        float pr[4] = { acc.x*2.f, acc.y*2.f, acc.z*2.f, acc.w*2.f };
        float4 o;
        float* ov = (float*)&o;
        #pragma unroll
        for (int k = 0; k < 4; k++) {
            int gi = (zq*4 + k) * NSLOT + sidx;
            float mm = mult[gi];
            float e  = __fmaf_rn(mm, pr[k], contam[gi]);   // exp = mult*fwd + contam
            ov[k] = mm * data[gi] / e;                     // mult * (data/exp)
        }
        ((float4*)zr)[sidx*4 + zq] = o;
    }
}

// ---------------- backprojection (exact adjoint, gather form) ---------------
// one thread = (pixel, phi-chunk). All 16 z accumulated; W computed once.
// Interior pixels skip the ix/iy bounds test (tent support implies validity).
__global__ void k_backproject(const float* __restrict__ zr, float* __restrict__ bp)
{
    int tid = blockIdx.x * blockDim.x + threadIdx.x;
    if (tid >= NCH * NPIX) return;
    int pix = tid % NPIX;
    int ch  = tid / NPIX;
    int i = pix / N2, j = pix % N2;
    float X = -199.f + 2.f * (float)i;
    float Y = -199.f + 2.f * (float)j;

    float acc[N0];
    #pragma unroll
    for (int k = 0; k < N0; k++) acc[k] = 0.f;

    const float inv_dr = (float)(222.0 / 400.0);
    float fi_f = (float)i, fj_f = (float)j;
    bool interior = (i >= 1 && i <= N1-2 && j >= 1 && j <= N2-2);

    int plo = ch * CHW;
    int phi_end = min(NPHI, plo + CHW);

    for (int phi = plo; phi < phi_end; phi++) {
        float c = d_COS[phi], s = d_SIN[phi];
        float lim = 2.f * (fabsf(c) + fabsf(s)) + 1e-2f;   // tight tent support
        float r0 = -X*s + Y*c;   // projection of voxel onto perp(phi)
        float t0 =  X*c + Y*s;   // projection onto dir(phi)
        int mlo = max(0,      (int)ceilf ((r0 + 200.f - lim) * inv_dr));
        int mhi = min(NRAD-1, (int)floorf((r0 + 200.f + lim) * inv_dr));
        int nlo = max(0,      (int)ceilf ((t0 + 350.f - lim) * 0.5f));
        int nhi = min(NT-1,   (int)floorf((t0 + 350.f + lim) * 0.5f));
        for (int m = mlo; m <= mhi; m++) {
            float rm  = d_RV[m];
            float rns = rm * (-s);
            float rc  = rm * c;
            float W = 0.f;
            if (interior) {
                for (int n = nlo; n <= nhi; n++) {
                    float tn = -350.f + 2.f * (float)n;
                    float ix = (__fmaf_rn(tn, c, rns) + 199.f) * 0.5f;
                    float iy = (__fmaf_rn(tn, s, rc ) + 199.f) * 0.5f;
                    float wx = 1.f - fabsf(ix - fi_f);
                    float wy = 1.f - fabsf(iy - fj_f);
                    if (wx > 0.f && wy > 0.f) W = __fmaf_rn(wx, wy, W);
                }
            } else {
                for (int n = nlo; n <= nhi; n++) {
                    float tn = -350.f + 2.f * (float)n;
                    float ix = (__fmaf_rn(tn, c, rns) + 199.f) * 0.5f;
                    float iy = (__fmaf_rn(tn, s, rc ) + 199.f) * 0.5f;
                    if (ix < 0.f || ix > 199.f || iy < 0.f || iy > 199.f) continue;
                    float wx = 1.f - fabsf(ix - fi_f);
                    float wy = 1.f - fabsf(iy - fj_f);
                    if (wx > 0.f && wy > 0.f) W = __fmaf_rn(wx, wy, W);
                }
            }
            if (W != 0.f) {
                const float4* zp = (const float4*)(zr + (phi*NRAD + m)*N0);
                float4 a = zp[0], b = zp[1], cc = zp[2], dd = zp[3];
                acc[0]  += W*a.x;  acc[1]  += W*a.y;  acc[2]  += W*a.z;  acc[3]  += W*a.w;
                acc[4]  += W*b.x;  acc[5]  += W*b.y;  acc[6]  += W*b.z;  acc[7]  += W*b.w;
                acc[8]  += W*cc.x; acc[9]  += W*cc.y; acc[10] += W*cc.z; acc[11] += W*cc.w;
                acc[12] += W*dd.x; acc[13] += W*dd.y; acc[14] += W*dd.z; acc[15] += W*dd.w;
            }
        }
    }
    float* dst = bp + ch * NVOX;
    #pragma unroll
    for (int k = 0; k < N0; k++)
        dst[k*NPIX + pix] = acc[k] * 2.f;   // * STEP
}

// ---------------- combine partial backprojections ---------------------------
__global__ void k_combine(const float* __restrict__ bp, float* __restrict__ g)
{
    int t = blockIdx.x * blockDim.x + threadIdx.x;
    if (t >= NVOX) return;
    float s = 0.f;
    #pragma unroll
    for (int c = 0; c < NCH; c++) s += bp[c*NVOX + t];
    g[t] = s;
}

// ---------------- final z-smoothing + MLEM update ---------------------------
__global__ void k_smooth_z_final(const float* __restrict__ gin,
                                 const float* __restrict__ x,
                                 const float* __restrict__ sens,
                                 float* __restrict__ out)
{
    int pix = blockIdx.x * blockDim.x + threadIdx.x;
    if (pix >= NPIX) return;
    float v[N0];
    #pragma unroll
    for (int z = 0; z < N0; z++) v[z] = gin[z*NPIX + pix];
    #pragma unroll
    for (int z = 0; z < N0; z++) {
        float s = 0.f;
        #pragma unroll
        for (int d = -GR; d <= GR; d++) {
            int m = z + d;
            if (m < 0)  m = -1 - m;
            if (m >= N0) m = 2*N0 - 1 - m;
            s += d_GW[d+GR] * v[m];
        }
        int gi = z*NPIX + pix;
        out[gi] = x[gi] * s / sens[gi];
    }
}

// ---------------- launch ----------------------------------------------------
extern "C" void kernel_launch(void* const* d_in, const int* in_sizes, int n_in,
                              void* d_out, int out_size)
{
    const float* x      = (const float*)d_in[0];
    const float* data   = (const float*)d_in[1];
    const float* contam = (const float*)d_in[2];
    const float* mult   = (const float*)d_in[3];
    const float* sens   = (const float*)d_in[4];
    float* out = (float*)d_out;

    float *buf0, *buf1, *st2, *zr, *bp;
    cudaGetSymbolAddress((void**)&buf0, d_buf0);
    cudaGetSymbolAddress((void**)&buf1, d_buf1);
    cudaGetSymbolAddress((void**)&st2,  d_st2);
    cudaGetSymbolAddress((void**)&zr,   d_zr);
    cudaGetSymbolAddress((void**)&bp,   d_bp);

    k_init<<<1, 256>>>();

    // forward: gauss3(x) -> paired transposed smoothed image
    k_smooth_z   <<<(NPIX + 255)/256, 256>>>(x, buf0);
    k_smooth_i   <<<(NVOX + 255)/256, 256>>>(buf0, buf1);
    k_smooth_j_t2<<<(NVOX + 255)/256, 256>>>(buf1, st2);

    // project + exp + ratio (fused, 8 lanes/ray)
    k_project<<<(NSLOT*8 + 255)/256, 256>>>(st2, data, contam, mult, zr);

    // adjoint: backproject (phi-chunked), combine, then gauss3 reversed
    k_backproject<<<(NCH*NPIX + 255)/256, 256>>>(zr, bp);
    k_combine<<<(NVOX + 255)/256, 256>>>(bp, buf0);
    k_smooth_j<<<(NVOX + 255)/256, 256>>>(buf0, buf1);
    k_smooth_i<<<(NVOX + 255)/256, 256>>>(buf1, buf0);
    k_smooth_z_final<<<(NPIX + 255)/256, 256>>>(buf0, x, sens, out);
}